// round 1
// baseline (speedup 1.0000x reference)
#include <cuda_runtime.h>
#include <cstdint>

// ---------------------------------------------------------------------------
// CategoricalGINEncoder on GB300 (sm_103a)
//   x = concat(emb_f[x_cat[:,f]])                       [N,256]
//   conv1: agg = x + segsum(x[src]->dst); h=relu(agg@w1a+b1a)@w1b+b1b
//   h = LN1(relu(h))
//   conv2: agg = h + segsum(h[src]->dst); o=relu(agg@w2a+b2a)@w2b+b2b
//   out = LN2(o)
// GEMMs: tf32 mma.sync (m16n8k8), fp32 accumulate.
// Aggregation: on-device CSR (by dst) built once, warp-per-row gather.
// ---------------------------------------------------------------------------

#define NMAX 100000
#define EMAX 1600000
#define DIM  256

__device__ float g_b0[(size_t)NMAX * DIM];
__device__ float g_b1[(size_t)NMAX * DIM];
__device__ float g_b2[(size_t)NMAX * DIM];
__device__ int   g_deg[NMAX];
__device__ int   g_rowptr[NMAX + 1];
__device__ int   g_cursor[NMAX];
__device__ int   g_csr[EMAX];

// ------------------------------- CSR build --------------------------------

__global__ void k_zero(int* __restrict__ p, int n) {
    int i = blockIdx.x * blockDim.x + threadIdx.x;
    if (i < n) p[i] = 0;
}

__global__ void k_count(const int* __restrict__ ei, int* __restrict__ deg, int E) {
    int e = blockIdx.x * blockDim.x + threadIdx.x;
    if (e < E) atomicAdd(&deg[ei[E + e]], 1);
}

// single-block exclusive scan (1024 threads, chunked)
__global__ void k_scan(const int* __restrict__ deg, int* __restrict__ rowptr,
                       int* __restrict__ cursor, int n) {
    __shared__ int sh[1024];
    int t = threadIdx.x;
    int chunk = (n + 1023) >> 10;
    int lo = t * chunk;
    int hi = min(lo + chunk, n);
    int s = 0;
    for (int i = lo; i < hi; ++i) s += deg[i];
    sh[t] = s;
    __syncthreads();
    for (int off = 1; off < 1024; off <<= 1) {
        int v = (t >= off) ? sh[t - off] : 0;
        __syncthreads();
        sh[t] += v;
        __syncthreads();
    }
    int run = (t == 0) ? 0 : sh[t - 1];
    for (int i = lo; i < hi; ++i) {
        rowptr[i] = run;
        cursor[i] = run;
        run += deg[i];
    }
    if (lo < n && hi == n) rowptr[n] = run;
}

__global__ void k_fill(const int* __restrict__ ei, int* __restrict__ cursor,
                       int* __restrict__ csr, int E) {
    int e = blockIdx.x * blockDim.x + threadIdx.x;
    if (e < E) {
        int s = ei[e];
        int d = ei[E + e];
        int p = atomicAdd(&cursor[d], 1);
        csr[p] = s;
    }
}

// ------------------------------- embedding --------------------------------

__global__ void k_embed(const int* __restrict__ xc,
                        const float* __restrict__ e0, const float* __restrict__ e1,
                        const float* __restrict__ e2, const float* __restrict__ e3,
                        float* __restrict__ out, int M) {
    int n = blockIdx.x;
    if (n >= M) return;
    int c = threadIdx.x;            // 0..255
    int f = c >> 6, j = c & 63;
    const float* et = (f == 0) ? e0 : (f == 1) ? e1 : (f == 2) ? e2 : e3;
    int cat = xc[n * 4 + f];
    out[(size_t)n * DIM + c] = et[cat * 64 + j];
}

// --------------------------- aggregation (GIN) ----------------------------
// y[i] = x[i] + sum_{e in row i} x[csr[e]]   (warp per row, 8 floats/lane)

__global__ void k_agg(const float* __restrict__ X, float* __restrict__ Y,
                      const int* __restrict__ rowptr, const int* __restrict__ csr,
                      int M) {
    int w = (blockIdx.x * blockDim.x + threadIdx.x) >> 5;
    int lane = threadIdx.x & 31;
    if (w >= M) return;
    const float4* xr = (const float4*)(X + (size_t)w * DIM);
    float4 a0 = xr[lane];
    float4 a1 = xr[lane + 32];
    int e = rowptr[w], end = rowptr[w + 1];
    for (; e < end; ++e) {
        int s = csr[e];
        const float4* xs = (const float4*)(X + (size_t)s * DIM);
        float4 u0 = xs[lane];
        float4 u1 = xs[lane + 32];
        a0.x += u0.x; a0.y += u0.y; a0.z += u0.z; a0.w += u0.w;
        a1.x += u1.x; a1.y += u1.y; a1.z += u1.z; a1.w += u1.w;
    }
    float4* yr = (float4*)(Y + (size_t)w * DIM);
    yr[lane] = a0;
    yr[lane + 32] = a1;
}

// ------------------------------ layer norm --------------------------------
// warp per row; optional leading relu

__global__ void k_ln(const float* __restrict__ X, float* __restrict__ Y,
                     const float* __restrict__ gam, const float* __restrict__ bet,
                     int M, int doRelu) {
    int row = (blockIdx.x * blockDim.x + threadIdx.x) >> 5;
    int lane = threadIdx.x & 31;
    if (row >= M) return;
    const float4* xr = (const float4*)(X + (size_t)row * DIM);
    float4 v0 = xr[lane];
    float4 v1 = xr[lane + 32];
    if (doRelu) {
        v0.x = fmaxf(v0.x, 0.f); v0.y = fmaxf(v0.y, 0.f);
        v0.z = fmaxf(v0.z, 0.f); v0.w = fmaxf(v0.w, 0.f);
        v1.x = fmaxf(v1.x, 0.f); v1.y = fmaxf(v1.y, 0.f);
        v1.z = fmaxf(v1.z, 0.f); v1.w = fmaxf(v1.w, 0.f);
    }
    float s  = v0.x + v0.y + v0.z + v0.w + v1.x + v1.y + v1.z + v1.w;
    float ss = v0.x * v0.x + v0.y * v0.y + v0.z * v0.z + v0.w * v0.w +
               v1.x * v1.x + v1.y * v1.y + v1.z * v1.z + v1.w * v1.w;
    #pragma unroll
    for (int o = 16; o >= 1; o >>= 1) {
        s  += __shfl_xor_sync(0xffffffffu, s, o);
        ss += __shfl_xor_sync(0xffffffffu, ss, o);
    }
    float mean = s * (1.f / 256.f);
    float var  = ss * (1.f / 256.f) - mean * mean;
    float rstd = rsqrtf(var + 1e-5f);
    const float4* g4 = (const float4*)gam;
    const float4* b4 = (const float4*)bet;
    float4 ga = g4[lane], gb = g4[lane + 32];
    float4 ba = b4[lane], bb = b4[lane + 32];
    float4 o0, o1;
    o0.x = (v0.x - mean) * rstd * ga.x + ba.x;
    o0.y = (v0.y - mean) * rstd * ga.y + ba.y;
    o0.z = (v0.z - mean) * rstd * ga.z + ba.z;
    o0.w = (v0.w - mean) * rstd * ga.w + ba.w;
    o1.x = (v1.x - mean) * rstd * gb.x + bb.x;
    o1.y = (v1.y - mean) * rstd * gb.y + bb.y;
    o1.z = (v1.z - mean) * rstd * gb.z + bb.z;
    o1.w = (v1.w - mean) * rstd * gb.w + bb.w;
    float4* yr = (float4*)(Y + (size_t)row * DIM);
    yr[lane] = o0;
    yr[lane + 32] = o1;
}

// ------------------------------- tf32 GEMM --------------------------------
// C[M,256] = act(A[M,256] @ W[256,256] + bias)
// Block tile 64x256, BK=32, 8 warps (2 along M x 4 along N), warp tile 32x64.
// Double-buffered smem, register-staged global loads, cvt->tf32 at STS.

#define APAD 36                  // 32 + 4 pad: conflict-free A fragment LDS
#define WPAD 264                 // 256 + 8 pad: conflict-free B fragment LDS
#define A_ST 2304                // 64*36 floats
#define W_ST 8448                // 32*264 floats
#define GEMM_SMEM_BYTES (2 * (A_ST + W_ST) * 4)

__device__ __forceinline__ float to_tf32(float x) {
    uint32_t u;
    asm("cvt.rna.tf32.f32 %0, %1;" : "=r"(u) : "f"(x));
    return __uint_as_float(u);
}

__device__ __forceinline__ void mma8(float* c, const uint32_t* a, const uint32_t* b) {
    asm volatile(
        "mma.sync.aligned.m16n8k8.row.col.f32.tf32.tf32.f32 "
        "{%0,%1,%2,%3},{%4,%5,%6,%7},{%8,%9},{%0,%1,%2,%3};\n"
        : "+f"(c[0]), "+f"(c[1]), "+f"(c[2]), "+f"(c[3])
        : "r"(a[0]), "r"(a[1]), "r"(a[2]), "r"(a[3]), "r"(b[0]), "r"(b[1]));
}

__global__ void __launch_bounds__(256) k_gemm(
    const float* __restrict__ A, const float* __restrict__ W,
    const float* __restrict__ bias, float* __restrict__ C, int M, int doRelu) {
    extern __shared__ float sm[];
    float* As = sm;               // [2][A_ST]
    float* Ws = sm + 2 * A_ST;    // [2][W_ST]

    const int tid  = threadIdx.x;
    const int warp = tid >> 5, lane = tid & 31;
    const int wm = warp >> 2;     // 0..1 (M)
    const int wn = warp & 3;      // 0..3 (N)
    const int g  = lane >> 2;     // 0..7
    const int tq = lane & 3;      // 0..3
    const long blockRow = (long)blockIdx.x * 64;

    float c[2][8][4];
    #pragma unroll
    for (int i = 0; i < 2; ++i)
        #pragma unroll
        for (int j = 0; j < 8; ++j)
            #pragma unroll
            for (int k = 0; k < 4; ++k) c[i][j][k] = 0.f;

    const int akq = tid & 7;      // A float4 slot in K
    const int wq  = tid & 63;     // W float4 slot in N

    float4 ra[2], rw[8];

    // prologue load (k0 = 0)
    #pragma unroll
    for (int i = 0; i < 2; ++i) {
        long r = blockRow + (tid >> 3) + i * 32;
        if (r > M - 1) r = M - 1;
        ra[i] = *(const float4*)(A + r * 256 + akq * 4);
    }
    #pragma unroll
    for (int i = 0; i < 8; ++i) {
        int wk = (tid >> 6) + i * 4;
        rw[i] = *(const float4*)(W + (long)wk * 256 + wq * 4);
    }
    {
        float* as = As;
        float* ws = Ws;
        #pragma unroll
        for (int i = 0; i < 2; ++i) {
            float4 v = ra[i];
            v.x = to_tf32(v.x); v.y = to_tf32(v.y);
            v.z = to_tf32(v.z); v.w = to_tf32(v.w);
            int row = (tid >> 3) + i * 32;
            *(float4*)(as + row * APAD + akq * 4) = v;
        }
        #pragma unroll
        for (int i = 0; i < 8; ++i) {
            float4 v = rw[i];
            v.x = to_tf32(v.x); v.y = to_tf32(v.y);
            v.z = to_tf32(v.z); v.w = to_tf32(v.w);
            int wk = (tid >> 6) + i * 4;
            *(float4*)(ws + wk * WPAD + wq * 4) = v;
        }
    }
    __syncthreads();

    #pragma unroll 1
    for (int it = 0; it < 8; ++it) {
        if (it < 7) {
            int k0 = (it + 1) * 32;
            #pragma unroll
            for (int i = 0; i < 2; ++i) {
                long r = blockRow + (tid >> 3) + i * 32;
                if (r > M - 1) r = M - 1;
                ra[i] = *(const float4*)(A + r * 256 + k0 + akq * 4);
            }
            #pragma unroll
            for (int i = 0; i < 8; ++i) {
                int wk = (tid >> 6) + i * 4;
                rw[i] = *(const float4*)(W + (long)(k0 + wk) * 256 + wq * 4);
            }
        }
        const float* as = As + (it & 1) * A_ST;
        const float* ws = Ws + (it & 1) * W_ST;
        #pragma unroll
        for (int kt = 0; kt < 4; ++kt) {
            int kb = kt * 8;
            uint32_t af[2][4], bf[8][2];
            #pragma unroll
            for (int mt = 0; mt < 2; ++mt) {
                int r0 = wm * 32 + mt * 16;
                af[mt][0] = __float_as_uint(as[(r0 + g)     * APAD + kb + tq]);
                af[mt][1] = __float_as_uint(as[(r0 + 8 + g) * APAD + kb + tq]);
                af[mt][2] = __float_as_uint(as[(r0 + g)     * APAD + kb + 4 + tq]);
                af[mt][3] = __float_as_uint(as[(r0 + 8 + g) * APAD + kb + 4 + tq]);
            }
            #pragma unroll
            for (int nt = 0; nt < 8; ++nt) {
                int n0 = wn * 64 + nt * 8;
                bf[nt][0] = __float_as_uint(ws[(kb + tq)     * WPAD + n0 + g]);
                bf[nt][1] = __float_as_uint(ws[(kb + 4 + tq) * WPAD + n0 + g]);
            }
            #pragma unroll
            for (int mt = 0; mt < 2; ++mt)
                #pragma unroll
                for (int nt = 0; nt < 8; ++nt)
                    mma8(c[mt][nt], af[mt], bf[nt]);
        }
        if (it < 7) {
            __syncthreads();
            float* asN = As + ((it + 1) & 1) * A_ST;
            float* wsN = Ws + ((it + 1) & 1) * W_ST;
            #pragma unroll
            for (int i = 0; i < 2; ++i) {
                float4 v = ra[i];
                v.x = to_tf32(v.x); v.y = to_tf32(v.y);
                v.z = to_tf32(v.z); v.w = to_tf32(v.w);
                int row = (tid >> 3) + i * 32;
                *(float4*)(asN + row * APAD + akq * 4) = v;
            }
            #pragma unroll
            for (int i = 0; i < 8; ++i) {
                float4 v = rw[i];
                v.x = to_tf32(v.x); v.y = to_tf32(v.y);
                v.z = to_tf32(v.z); v.w = to_tf32(v.w);
                int wk = (tid >> 6) + i * 4;
                *(float4*)(wsN + wk * WPAD + wq * 4) = v;
            }
            __syncthreads();
        }
    }

    // epilogue: bias (+relu), guarded stores
    #pragma unroll
    for (int mt = 0; mt < 2; ++mt) {
        long rb = blockRow + wm * 32 + mt * 16;
        long r0 = rb + g;
        long r1 = rb + 8 + g;
        #pragma unroll
        for (int nt = 0; nt < 8; ++nt) {
            int col = wn * 64 + nt * 8 + tq * 2;
            float2 bb = *(const float2*)(bias + col);
            float v0 = c[mt][nt][0] + bb.x;
            float v1 = c[mt][nt][1] + bb.y;
            float v2 = c[mt][nt][2] + bb.x;
            float v3 = c[mt][nt][3] + bb.y;
            if (doRelu) {
                v0 = fmaxf(v0, 0.f); v1 = fmaxf(v1, 0.f);
                v2 = fmaxf(v2, 0.f); v3 = fmaxf(v3, 0.f);
            }
            if (r0 < M) { float2 t = {v0, v1}; *(float2*)(C + r0 * 256 + col) = t; }
            if (r1 < M) { float2 t = {v2, v3}; *(float2*)(C + r1 * 256 + col) = t; }
        }
    }
}

// --------------------------------- driver ---------------------------------

extern "C" void kernel_launch(void* const* d_in, const int* in_sizes, int n_in,
                              void* d_out, int out_size) {
    const int*   xcat = (const int*)d_in[0];
    const int*   ei   = (const int*)d_in[1];
    const float* e0   = (const float*)d_in[2];
    const float* e1   = (const float*)d_in[3];
    const float* e2   = (const float*)d_in[4];
    const float* e3   = (const float*)d_in[5];
    const float* w1a  = (const float*)d_in[6];
    const float* b1a  = (const float*)d_in[7];
    const float* w1b  = (const float*)d_in[8];
    const float* b1b  = (const float*)d_in[9];
    const float* w2a  = (const float*)d_in[10];
    const float* b2a  = (const float*)d_in[11];
    const float* w2b  = (const float*)d_in[12];
    const float* b2b  = (const float*)d_in[13];
    const float* ln1g = (const float*)d_in[14];
    const float* ln1b = (const float*)d_in[15];
    const float* ln2g = (const float*)d_in[16];
    const float* ln2b = (const float*)d_in[17];

    int M = in_sizes[0] / 4;
    int E = in_sizes[1] / 2;

    float *b0, *b1, *b2;
    int *deg, *rowptr, *cursor, *csr;
    cudaGetSymbolAddress((void**)&b0, g_b0);
    cudaGetSymbolAddress((void**)&b1, g_b1);
    cudaGetSymbolAddress((void**)&b2, g_b2);
    cudaGetSymbolAddress((void**)&deg, g_deg);
    cudaGetSymbolAddress((void**)&rowptr, g_rowptr);
    cudaGetSymbolAddress((void**)&cursor, g_cursor);
    cudaGetSymbolAddress((void**)&csr, g_csr);

    cudaFuncSetAttribute(k_gemm, cudaFuncAttributeMaxDynamicSharedMemorySize,
                         GEMM_SMEM_BYTES);

    int rowGrid = (M + 7) / 8;      // warp-per-row kernels, 8 warps/block
    int gemmGrid = (M + 63) / 64;

    // CSR by dst (built once, used by both convs)
    k_zero<<<(M + 255) / 256, 256>>>(deg, M);
    k_count<<<(E + 255) / 256, 256>>>(ei, deg, E);
    k_scan<<<1, 1024>>>(deg, rowptr, cursor, M);
    k_fill<<<(E + 255) / 256, 256>>>(ei, cursor, csr, E);

    // embedding -> b0
    k_embed<<<M, 256>>>(xcat, e0, e1, e2, e3, b0, M);

    // conv1
    k_agg<<<rowGrid, 256>>>(b0, b1, rowptr, csr, M);
    k_gemm<<<gemmGrid, 256, GEMM_SMEM_BYTES>>>(b1, w1a, b1a, b2, M, 1);
    k_gemm<<<gemmGrid, 256, GEMM_SMEM_BYTES>>>(b2, w1b, b1b, b1, M, 0);
    k_ln<<<rowGrid, 256>>>(b1, b0, ln1g, ln1b, M, 1);   // relu + LN1

    // conv2
    k_agg<<<rowGrid, 256>>>(b0, b2, rowptr, csr, M);
    k_gemm<<<gemmGrid, 256, GEMM_SMEM_BYTES>>>(b2, w2a, b2a, b1, M, 1);
    k_gemm<<<gemmGrid, 256, GEMM_SMEM_BYTES>>>(b1, w2b, b2b, b2, M, 0);
    k_ln<<<rowGrid, 256>>>(b2, (float*)d_out, ln2g, ln2b, M, 0);  // LN2
}

// round 2
// speedup vs baseline: 1.0211x; 1.0211x over previous
#include <cuda_runtime.h>
#include <cstdint>

// ---------------------------------------------------------------------------
// CategoricalGINEncoder on GB300 (sm_103a) — round 2
//  - Fused per-conv kernel: O = LN( [relu] ( relu(A@Wa+ba) @ Wb + bb ) )
//    (one 64x256 row-tile per block; H kept in smem as tf32; LN block-local)
//  - Aggregation: CSR gather, unroll-2 prefetch for MLP.
// ---------------------------------------------------------------------------

#define NMAX 100000
#define EMAX 1600000
#define DIM  256

__device__ float g_b0[(size_t)NMAX * DIM];
__device__ float g_b1[(size_t)NMAX * DIM];
__device__ int   g_deg[NMAX];
__device__ int   g_rowptr[NMAX + 1];
__device__ int   g_cursor[NMAX];
__device__ int   g_csr[EMAX];

// ------------------------------- CSR build --------------------------------

__global__ void k_zero(int* __restrict__ p, int n) {
    int i = blockIdx.x * blockDim.x + threadIdx.x;
    if (i < n) p[i] = 0;
}

__global__ void k_count(const int* __restrict__ ei, int* __restrict__ deg, int E) {
    int e = blockIdx.x * blockDim.x + threadIdx.x;
    if (e < E) atomicAdd(&deg[ei[E + e]], 1);
}

__global__ void k_scan(const int* __restrict__ deg, int* __restrict__ rowptr,
                       int* __restrict__ cursor, int n) {
    __shared__ int sh[1024];
    int t = threadIdx.x;
    int chunk = (n + 1023) >> 10;
    int lo = t * chunk;
    int hi = min(lo + chunk, n);
    int s = 0;
    for (int i = lo; i < hi; ++i) s += deg[i];
    sh[t] = s;
    __syncthreads();
    for (int off = 1; off < 1024; off <<= 1) {
        int v = (t >= off) ? sh[t - off] : 0;
        __syncthreads();
        sh[t] += v;
        __syncthreads();
    }
    int run = (t == 0) ? 0 : sh[t - 1];
    for (int i = lo; i < hi; ++i) {
        rowptr[i] = run;
        cursor[i] = run;
        run += deg[i];
    }
    if (lo < n && hi == n) rowptr[n] = run;
}

__global__ void k_fill(const int* __restrict__ ei, int* __restrict__ cursor,
                       int* __restrict__ csr, int E) {
    int e = blockIdx.x * blockDim.x + threadIdx.x;
    if (e < E) {
        int s = ei[e];
        int d = ei[E + e];
        int p = atomicAdd(&cursor[d], 1);
        csr[p] = s;
    }
}

// ------------------------------- embedding --------------------------------

__global__ void k_embed(const int* __restrict__ xc,
                        const float* __restrict__ e0, const float* __restrict__ e1,
                        const float* __restrict__ e2, const float* __restrict__ e3,
                        float* __restrict__ out, int M) {
    int n = blockIdx.x;
    if (n >= M) return;
    int c = threadIdx.x;            // 0..255
    int f = c >> 6, j = c & 63;
    const float* et = (f == 0) ? e0 : (f == 1) ? e1 : (f == 2) ? e2 : e3;
    int cat = xc[n * 4 + f];
    out[(size_t)n * DIM + c] = et[cat * 64 + j];
}

// --------------------------- aggregation (GIN) ----------------------------
// y[i] = x[i] + sum_{e in row i} x[csr[e]]   (warp per row, unroll-2 prefetch)

__global__ void k_agg(const float* __restrict__ X, float* __restrict__ Y,
                      const int* __restrict__ rowptr, const int* __restrict__ csr,
                      int M) {
    int w = (blockIdx.x * blockDim.x + threadIdx.x) >> 5;
    int lane = threadIdx.x & 31;
    if (w >= M) return;
    const float4* xr = (const float4*)(X + (size_t)w * DIM);
    float4 a0 = xr[lane];
    float4 a1 = xr[lane + 32];
    int e = rowptr[w], end = rowptr[w + 1];
    for (; e + 1 < end; e += 2) {
        int s0 = csr[e];
        int s1 = csr[e + 1];
        const float4* x0 = (const float4*)(X + (size_t)s0 * DIM);
        const float4* x1 = (const float4*)(X + (size_t)s1 * DIM);
        float4 u0 = x0[lane];
        float4 u1 = x0[lane + 32];
        float4 v0 = x1[lane];
        float4 v1 = x1[lane + 32];
        a0.x += u0.x; a0.y += u0.y; a0.z += u0.z; a0.w += u0.w;
        a1.x += u1.x; a1.y += u1.y; a1.z += u1.z; a1.w += u1.w;
        a0.x += v0.x; a0.y += v0.y; a0.z += v0.z; a0.w += v0.w;
        a1.x += v1.x; a1.y += v1.y; a1.z += v1.z; a1.w += v1.w;
    }
    if (e < end) {
        int s = csr[e];
        const float4* xs = (const float4*)(X + (size_t)s * DIM);
        float4 u0 = xs[lane];
        float4 u1 = xs[lane + 32];
        a0.x += u0.x; a0.y += u0.y; a0.z += u0.z; a0.w += u0.w;
        a1.x += u1.x; a1.y += u1.y; a1.z += u1.z; a1.w += u1.w;
    }
    float4* yr = (float4*)(Y + (size_t)w * DIM);
    yr[lane] = a0;
    yr[lane + 32] = a1;
}

// --------------------------- fused conv kernel -----------------------------
// Per 64-row tile:
//   H = relu(A @ Wa + ba)        (tf32 mma, H -> smem as tf32)
//   O = H @ Wb + bb
//   out = LN( reluBeforeLN ? relu(O) : O )
// 8 warps (2 M x 4 N), warp tile 32x64, BK=32, W double-buffered.

#define XP    260                  // A/H tile row stride (floats); 260%32=4
#define XS_SZ (64 * XP)            // 16640 floats
#define WPAD  264                  // W chunk row stride; 264%32=8
#define W_ST  (32 * WPAD)          // 8448 floats
#define MLP_SMEM_BYTES ((XS_SZ + 2 * W_ST) * 4)

__device__ __forceinline__ float to_tf32(float x) {
    uint32_t u;
    asm("cvt.rna.tf32.f32 %0, %1;" : "=r"(u) : "f"(x));
    return __uint_as_float(u);
}

__device__ __forceinline__ void mma8(float* c, const uint32_t* a, const uint32_t* b) {
    asm volatile(
        "mma.sync.aligned.m16n8k8.row.col.f32.tf32.tf32.f32 "
        "{%0,%1,%2,%3},{%4,%5,%6,%7},{%8,%9},{%0,%1,%2,%3};\n"
        : "+f"(c[0]), "+f"(c[1]), "+f"(c[2]), "+f"(c[3])
        : "r"(a[0]), "r"(a[1]), "r"(a[2]), "r"(a[3]), "r"(b[0]), "r"(b[1]));
}

__global__ void __launch_bounds__(256) k_mlp(
    const float* __restrict__ A,
    const float* __restrict__ Wa, const float* __restrict__ ba,
    const float* __restrict__ Wb, const float* __restrict__ bb,
    const float* __restrict__ lng, const float* __restrict__ lnb,
    float* __restrict__ Out, int M, int reluBeforeLN) {
    extern __shared__ float sm[];
    float* XS = sm;                 // 64 x XP  (A tile, then H tile, then O tile)
    float* WS = sm + XS_SZ;         // 2 x W_ST

    const int tid  = threadIdx.x;
    const int warp = tid >> 5, lane = tid & 31;
    const int wm = warp >> 2;       // 0..1
    const int wn = warp & 3;        // 0..3
    const int g  = lane >> 2;       // 0..7
    const int tq = lane & 3;        // 0..3
    const long blockRow = (long)blockIdx.x * 64;

    const int wq = tid & 63;        // W float4 col slot
    const int wkb = tid >> 6;       // W k-row base (0..3)

    float c[2][8][4];
    float4 rw[8];

    // ---- stage A tile (64x256) into XS as tf32 ----
    #pragma unroll
    for (int i = 0; i < 16; ++i) {
        int id = i * 256 + tid;         // float4 id, 64 per row
        int row = id >> 6;
        int c4 = id & 63;
        long r = blockRow + row;
        if (r > M - 1) r = M - 1;
        float4 v = *(const float4*)(A + r * 256 + c4 * 4);
        v.x = to_tf32(v.x); v.y = to_tf32(v.y);
        v.z = to_tf32(v.z); v.w = to_tf32(v.w);
        *(float4*)(XS + row * XP + c4 * 4) = v;
    }

    // ================= PHASE 1: H = relu(A @ Wa + ba) =================
    #pragma unroll
    for (int i = 0; i < 2; ++i)
        #pragma unroll
        for (int j = 0; j < 8; ++j)
            #pragma unroll
            for (int k = 0; k < 4; ++k) c[i][j][k] = 0.f;

    // prologue: Wa chunk 0 -> WS[0]
    #pragma unroll
    for (int i = 0; i < 8; ++i) {
        int wk = wkb + i * 4;
        rw[i] = *(const float4*)(Wa + (long)wk * 256 + wq * 4);
    }
    #pragma unroll
    for (int i = 0; i < 8; ++i) {
        float4 v = rw[i];
        v.x = to_tf32(v.x); v.y = to_tf32(v.y);
        v.z = to_tf32(v.z); v.w = to_tf32(v.w);
        int wk = wkb + i * 4;
        *(float4*)(WS + wk * WPAD + wq * 4) = v;
    }
    __syncthreads();

    #pragma unroll 1
    for (int it = 0; it < 8; ++it) {
        if (it < 7) {
            int k0 = (it + 1) * 32;
            #pragma unroll
            for (int i = 0; i < 8; ++i) {
                int wk = wkb + i * 4;
                rw[i] = *(const float4*)(Wa + (long)(k0 + wk) * 256 + wq * 4);
            }
        }
        const float* ws = WS + (it & 1) * W_ST;
        #pragma unroll
        for (int kt = 0; kt < 4; ++kt) {
            int kb = it * 32 + kt * 8;      // global k in XS
            int kw = kt * 8;                // k in W chunk
            uint32_t af[2][4], bf[8][2];
            #pragma unroll
            for (int mt = 0; mt < 2; ++mt) {
                int r0 = wm * 32 + mt * 16;
                af[mt][0] = __float_as_uint(XS[(r0 + g)     * XP + kb + tq]);
                af[mt][1] = __float_as_uint(XS[(r0 + 8 + g) * XP + kb + tq]);
                af[mt][2] = __float_as_uint(XS[(r0 + g)     * XP + kb + 4 + tq]);
                af[mt][3] = __float_as_uint(XS[(r0 + 8 + g) * XP + kb + 4 + tq]);
            }
            #pragma unroll
            for (int nt = 0; nt < 8; ++nt) {
                int n0 = wn * 64 + nt * 8;
                bf[nt][0] = __float_as_uint(ws[(kw + tq)     * WPAD + n0 + g]);
                bf[nt][1] = __float_as_uint(ws[(kw + 4 + tq) * WPAD + n0 + g]);
            }
            #pragma unroll
            for (int mt = 0; mt < 2; ++mt)
                #pragma unroll
                for (int nt = 0; nt < 8; ++nt)
                    mma8(c[mt][nt], af[mt], bf[nt]);
        }
        if (it < 7) {
            __syncthreads();
            float* wsN = WS + ((it + 1) & 1) * W_ST;
            #pragma unroll
            for (int i = 0; i < 8; ++i) {
                float4 v = rw[i];
                v.x = to_tf32(v.x); v.y = to_tf32(v.y);
                v.z = to_tf32(v.z); v.w = to_tf32(v.w);
                int wk = wkb + i * 4;
                *(float4*)(wsN + wk * WPAD + wq * 4) = v;
            }
            __syncthreads();
        }
    }

    // bias + relu, then store H (tf32) into XS (overwrites A tile)
    __syncthreads();    // all A reads done
    #pragma unroll
    for (int mt = 0; mt < 2; ++mt) {
        int r0 = wm * 32 + mt * 16;
        #pragma unroll
        for (int nt = 0; nt < 8; ++nt) {
            int col = wn * 64 + nt * 8 + tq * 2;
            float2 bv = *(const float2*)(ba + col);
            float v0 = fmaxf(c[mt][nt][0] + bv.x, 0.f);
            float v1 = fmaxf(c[mt][nt][1] + bv.y, 0.f);
            float v2 = fmaxf(c[mt][nt][2] + bv.x, 0.f);
            float v3 = fmaxf(c[mt][nt][3] + bv.y, 0.f);
            XS[(r0 + g)     * XP + col]     = to_tf32(v0);
            XS[(r0 + g)     * XP + col + 1] = to_tf32(v1);
            XS[(r0 + 8 + g) * XP + col]     = to_tf32(v2);
            XS[(r0 + 8 + g) * XP + col + 1] = to_tf32(v3);
        }
    }

    // prologue: Wb chunk 0 -> WS[0]
    #pragma unroll
    for (int i = 0; i < 8; ++i) {
        int wk = wkb + i * 4;
        rw[i] = *(const float4*)(Wb + (long)wk * 256 + wq * 4);
    }
    #pragma unroll
    for (int i = 0; i < 8; ++i) {
        float4 v = rw[i];
        v.x = to_tf32(v.x); v.y = to_tf32(v.y);
        v.z = to_tf32(v.z); v.w = to_tf32(v.w);
        int wk = wkb + i * 4;
        *(float4*)(WS + wk * WPAD + wq * 4) = v;
    }
    __syncthreads();

    // ================= PHASE 2: O = H @ Wb + bb =================
    #pragma unroll
    for (int i = 0; i < 2; ++i)
        #pragma unroll
        for (int j = 0; j < 8; ++j)
            #pragma unroll
            for (int k = 0; k < 4; ++k) c[i][j][k] = 0.f;

    #pragma unroll 1
    for (int it = 0; it < 8; ++it) {
        if (it < 7) {
            int k0 = (it + 1) * 32;
            #pragma unroll
            for (int i = 0; i < 8; ++i) {
                int wk = wkb + i * 4;
                rw[i] = *(const float4*)(Wb + (long)(k0 + wk) * 256 + wq * 4);
            }
        }
        const float* ws = WS + (it & 1) * W_ST;
        #pragma unroll
        for (int kt = 0; kt < 4; ++kt) {
            int kb = it * 32 + kt * 8;
            int kw = kt * 8;
            uint32_t af[2][4], bf[8][2];
            #pragma unroll
            for (int mt = 0; mt < 2; ++mt) {
                int r0 = wm * 32 + mt * 16;
                af[mt][0] = __float_as_uint(XS[(r0 + g)     * XP + kb + tq]);
                af[mt][1] = __float_as_uint(XS[(r0 + 8 + g) * XP + kb + tq]);
                af[mt][2] = __float_as_uint(XS[(r0 + g)     * XP + kb + 4 + tq]);
                af[mt][3] = __float_as_uint(XS[(r0 + 8 + g) * XP + kb + 4 + tq]);
            }
            #pragma unroll
            for (int nt = 0; nt < 8; ++nt) {
                int n0 = wn * 64 + nt * 8;
                bf[nt][0] = __float_as_uint(ws[(kw + tq)     * WPAD + n0 + g]);
                bf[nt][1] = __float_as_uint(ws[(kw + 4 + tq) * WPAD + n0 + g]);
            }
            #pragma unroll
            for (int mt = 0; mt < 2; ++mt)
                #pragma unroll
                for (int nt = 0; nt < 8; ++nt)
                    mma8(c[mt][nt], af[mt], bf[nt]);
        }
        if (it < 7) {
            __syncthreads();
            float* wsN = WS + ((it + 1) & 1) * W_ST;
            #pragma unroll
            for (int i = 0; i < 8; ++i) {
                float4 v = rw[i];
                v.x = to_tf32(v.x); v.y = to_tf32(v.y);
                v.z = to_tf32(v.z); v.w = to_tf32(v.w);
                int wk = wkb + i * 4;
                *(float4*)(wsN + wk * WPAD + wq * 4) = v;
            }
            __syncthreads();
        }
    }

    // ================= PHASE 3: bias (+relu) + LN =================
    __syncthreads();    // all H reads done; reuse XS for O (fp32)
    #pragma unroll
    for (int mt = 0; mt < 2; ++mt) {
        int r0 = wm * 32 + mt * 16;
        #pragma unroll
        for (int nt = 0; nt < 8; ++nt) {
            int col = wn * 64 + nt * 8 + tq * 2;
            float2 bv = *(const float2*)(bb + col);
            float v0 = c[mt][nt][0] + bv.x;
            float v1 = c[mt][nt][1] + bv.y;
            float v2 = c[mt][nt][2] + bv.x;
            float v3 = c[mt][nt][3] + bv.y;
            if (reluBeforeLN) {
                v0 = fmaxf(v0, 0.f); v1 = fmaxf(v1, 0.f);
                v2 = fmaxf(v2, 0.f); v3 = fmaxf(v3, 0.f);
            }
            XS[(r0 + g)     * XP + col]     = v0;
            XS[(r0 + g)     * XP + col + 1] = v1;
            XS[(r0 + 8 + g) * XP + col]     = v2;
            XS[(r0 + 8 + g) * XP + col + 1] = v3;
        }
    }
    __syncthreads();

    // warp-per-row LN: warp handles rows warp*8 .. warp*8+7; lane owns 8 cols
    {
        float4 ga = *(const float4*)(lng + lane * 8);
        float4 gb = *(const float4*)(lng + lane * 8 + 4);
        float4 bta = *(const float4*)(lnb + lane * 8);
        float4 btb = *(const float4*)(lnb + lane * 8 + 4);
        #pragma unroll 1
        for (int i = 0; i < 8; ++i) {
            int row = warp * 8 + i;
            long grow = blockRow + row;
            float4 v0 = *(const float4*)(XS + row * XP + lane * 8);
            float4 v1 = *(const float4*)(XS + row * XP + lane * 8 + 4);
            float s  = v0.x + v0.y + v0.z + v0.w + v1.x + v1.y + v1.z + v1.w;
            float ss = v0.x * v0.x + v0.y * v0.y + v0.z * v0.z + v0.w * v0.w +
                       v1.x * v1.x + v1.y * v1.y + v1.z * v1.z + v1.w * v1.w;
            #pragma unroll
            for (int o = 16; o >= 1; o >>= 1) {
                s  += __shfl_xor_sync(0xffffffffu, s, o);
                ss += __shfl_xor_sync(0xffffffffu, ss, o);
            }
            float mean = s * (1.f / 256.f);
            float var  = ss * (1.f / 256.f) - mean * mean;
            float rstd = rsqrtf(var + 1e-5f);
            if (grow < M) {
                float4 o0, o1;
                o0.x = (v0.x - mean) * rstd * ga.x + bta.x;
                o0.y = (v0.y - mean) * rstd * ga.y + bta.y;
                o0.z = (v0.z - mean) * rstd * ga.z + bta.z;
                o0.w = (v0.w - mean) * rstd * ga.w + bta.w;
                o1.x = (v1.x - mean) * rstd * gb.x + btb.x;
                o1.y = (v1.y - mean) * rstd * gb.y + btb.y;
                o1.z = (v1.z - mean) * rstd * gb.z + btb.z;
                o1.w = (v1.w - mean) * rstd * gb.w + btb.w;
                *(float4*)(Out + grow * 256 + lane * 8)     = o0;
                *(float4*)(Out + grow * 256 + lane * 8 + 4) = o1;
            }
        }
    }
}

// --------------------------------- driver ---------------------------------

extern "C" void kernel_launch(void* const* d_in, const int* in_sizes, int n_in,
                              void* d_out, int out_size) {
    const int*   xcat = (const int*)d_in[0];
    const int*   ei   = (const int*)d_in[1];
    const float* e0   = (const float*)d_in[2];
    const float* e1   = (const float*)d_in[3];
    const float* e2   = (const float*)d_in[4];
    const float* e3   = (const float*)d_in[5];
    const float* w1a  = (const float*)d_in[6];
    const float* b1a  = (const float*)d_in[7];
    const float* w1b  = (const float*)d_in[8];
    const float* b1b  = (const float*)d_in[9];
    const float* w2a  = (const float*)d_in[10];
    const float* b2a  = (const float*)d_in[11];
    const float* w2b  = (const float*)d_in[12];
    const float* b2b  = (const float*)d_in[13];
    const float* ln1g = (const float*)d_in[14];
    const float* ln1b = (const float*)d_in[15];
    const float* ln2g = (const float*)d_in[16];
    const float* ln2b = (const float*)d_in[17];

    int M = in_sizes[0] / 4;
    int E = in_sizes[1] / 2;

    float *b0, *b1;
    int *deg, *rowptr, *cursor, *csr;
    cudaGetSymbolAddress((void**)&b0, g_b0);
    cudaGetSymbolAddress((void**)&b1, g_b1);
    cudaGetSymbolAddress((void**)&deg, g_deg);
    cudaGetSymbolAddress((void**)&rowptr, g_rowptr);
    cudaGetSymbolAddress((void**)&cursor, g_cursor);
    cudaGetSymbolAddress((void**)&csr, g_csr);

    cudaFuncSetAttribute(k_mlp, cudaFuncAttributeMaxDynamicSharedMemorySize,
                         MLP_SMEM_BYTES);

    int rowGrid = (M + 7) / 8;
    int mlpGrid = (M + 63) / 64;

    // CSR by dst (rebuilt each call; deterministic)
    k_zero<<<(M + 255) / 256, 256>>>(deg, M);
    k_count<<<(E + 255) / 256, 256>>>(ei, deg, E);
    k_scan<<<1, 1024>>>(deg, rowptr, cursor, M);
    k_fill<<<(E + 255) / 256, 256>>>(ei, cursor, csr, E);

    // embedding -> b0
    k_embed<<<M, 256>>>(xcat, e0, e1, e2, e3, b0, M);

    // conv1: agg(b0)->b1 ; fused MLP+relu+LN1 -> b0
    k_agg<<<rowGrid, 256>>>(b0, b1, rowptr, csr, M);
    k_mlp<<<mlpGrid, 256, MLP_SMEM_BYTES>>>(b1, w1a, b1a, w1b, b1b,
                                            ln1g, ln1b, b0, M, 1);

    // conv2: agg(b0)->b1 ; fused MLP+LN2 -> d_out
    k_agg<<<rowGrid, 256>>>(b0, b1, rowptr, csr, M);
    k_mlp<<<mlpGrid, 256, MLP_SMEM_BYTES>>>(b1, w2a, b2a, w2b, b2b,
                                            ln2g, ln2b, (float*)d_out, M, 0);
}

// round 3
// speedup vs baseline: 1.2489x; 1.2230x over previous
#include <cuda_runtime.h>
#include <cstdint>

// ---------------------------------------------------------------------------
// CategoricalGINEncoder on GB300 (sm_103a) — round 3
//  Algebraic restructure (agg is linear, so agg(x)@W == agg(x@W)):
//   T_f = emb_f @ W1a_f          (4 tiny GEMMs -> 4MB table)
//   z0  = sum_f T_f[cat_f]       (lookup-sum; replaces embed + GEMM1)
//   a1  = agg(z0)
//   k_conv1: t=relu(a1+b1a); g=t@W1b+b1b; h=LN1(relu(g)); u=h@W2a -> gmem
//   a2  = agg(u)
//   k_conv2: t=relu(a2+b2a); o=t@W2b+b2b; out=LN2(o)
//  GEMM: tf32 mma.sync, 64x256 tile, BK=16 single-buffer W (2 CTAs/SM).
// ---------------------------------------------------------------------------

#define NMAX 100000
#define EMAX 1600000
#define DIM  256

__device__ float g_b0[(size_t)NMAX * DIM];
__device__ float g_b1[(size_t)NMAX * DIM];
__device__ float g_tab[(size_t)4 * 1024 * DIM];
__device__ int   g_deg[NMAX];
__device__ int   g_rowptr[NMAX + 1];
__device__ int   g_cursor[NMAX];
__device__ int   g_csr[EMAX];

// ------------------------------- CSR build --------------------------------

__global__ void k_zero(int* __restrict__ p, int n) {
    int i = blockIdx.x * blockDim.x + threadIdx.x;
    if (i < n) p[i] = 0;
}

__global__ void k_count(const int* __restrict__ ei, int* __restrict__ deg, int E) {
    int e = blockIdx.x * blockDim.x + threadIdx.x;
    if (e < E) atomicAdd(&deg[ei[E + e]], 1);
}

__global__ void k_scan(const int* __restrict__ deg, int* __restrict__ rowptr,
                       int* __restrict__ cursor, int n) {
    __shared__ int sh[1024];
    int t = threadIdx.x;
    int chunk = (n + 1023) >> 10;
    int lo = t * chunk;
    int hi = min(lo + chunk, n);
    int s = 0;
    for (int i = lo; i < hi; ++i) s += deg[i];
    sh[t] = s;
    __syncthreads();
    for (int off = 1; off < 1024; off <<= 1) {
        int v = (t >= off) ? sh[t - off] : 0;
        __syncthreads();
        sh[t] += v;
        __syncthreads();
    }
    int run = (t == 0) ? 0 : sh[t - 1];
    for (int i = lo; i < hi; ++i) {
        rowptr[i] = run;
        cursor[i] = run;
        run += deg[i];
    }
    if (lo < n && hi == n) rowptr[n] = run;
}

__global__ void k_fill(const int* __restrict__ ei, int* __restrict__ cursor,
                       int* __restrict__ csr, int E) {
    int e = blockIdx.x * blockDim.x + threadIdx.x;
    if (e < E) {
        int s = ei[e];
        int d = ei[E + e];
        int p = atomicAdd(&cursor[d], 1);
        csr[p] = s;
    }
}

// ------------------------ embedding tables T_f ------------------------------
// T[f][v][c] = sum_k emb_f[v][k] * W1a[64f+k][c]   (fp32 FFMA; tiny)

__global__ void k_tab(const float* __restrict__ e0, const float* __restrict__ e1,
                      const float* __restrict__ e2, const float* __restrict__ e3,
                      const float* __restrict__ w1a, float* __restrict__ T, int V) {
    int f = blockIdx.y;
    const float* emb = (f == 0) ? e0 : (f == 1) ? e1 : (f == 2) ? e2 : e3;
    int v0 = blockIdx.x * 16;
    __shared__ float es[16 * 64];
    int tid = threadIdx.x;
    #pragma unroll
    for (int i = 0; i < 4; ++i) {
        int idx = i * 256 + tid;
        int v = idx >> 6, k = idx & 63;
        es[idx] = (v0 + v < V) ? emb[(v0 + v) * 64 + k] : 0.f;
    }
    __syncthreads();
    float acc[16];
    #pragma unroll
    for (int v = 0; v < 16; ++v) acc[v] = 0.f;
    int c = tid;
    #pragma unroll 4
    for (int k = 0; k < 64; ++k) {
        float w = w1a[(f * 64 + k) * 256 + c];
        #pragma unroll
        for (int v = 0; v < 16; ++v) acc[v] = fmaf(es[v * 64 + k], w, acc[v]);
    }
    #pragma unroll
    for (int v = 0; v < 16; ++v)
        if (v0 + v < V) T[((size_t)f * 1024 + v0 + v) * 256 + c] = acc[v];
}

// z0[i] = sum_f T_f[cat_f[i]]
__global__ void k_z0(const int* __restrict__ xc, const float* __restrict__ T,
                     float* __restrict__ Z, int M) {
    int idx = blockIdx.x * blockDim.x + threadIdx.x;
    if (idx >= M * 64) return;
    int node = idx >> 6;
    int c4 = idx & 63;
    int c0 = xc[node * 4 + 0];
    int c1 = xc[node * 4 + 1];
    int c2 = xc[node * 4 + 2];
    int c3 = xc[node * 4 + 3];
    const float4* t0 = (const float4*)(T + ((size_t)0 * 1024 + c0) * 256);
    const float4* t1 = (const float4*)(T + ((size_t)1 * 1024 + c1) * 256);
    const float4* t2 = (const float4*)(T + ((size_t)2 * 1024 + c2) * 256);
    const float4* t3 = (const float4*)(T + ((size_t)3 * 1024 + c3) * 256);
    float4 a = t0[c4], b = t1[c4], c = t2[c4], d = t3[c4];
    float4 r;
    r.x = a.x + b.x + c.x + d.x;
    r.y = a.y + b.y + c.y + d.y;
    r.z = a.z + b.z + c.z + d.z;
    r.w = a.w + b.w + c.w + d.w;
    ((float4*)(Z + (size_t)node * 256))[c4] = r;
}

// --------------------------- aggregation (GIN) ----------------------------

__global__ void k_agg(const float* __restrict__ X, float* __restrict__ Y,
                      const int* __restrict__ rowptr, const int* __restrict__ csr,
                      int M) {
    int w = (blockIdx.x * blockDim.x + threadIdx.x) >> 5;
    int lane = threadIdx.x & 31;
    if (w >= M) return;
    const float4* xr = (const float4*)(X + (size_t)w * DIM);
    float4 a0 = xr[lane];
    float4 a1 = xr[lane + 32];
    int e = rowptr[w], end = rowptr[w + 1];
    for (; e + 1 < end; e += 2) {
        int s0 = csr[e];
        int s1 = csr[e + 1];
        const float4* x0 = (const float4*)(X + (size_t)s0 * DIM);
        const float4* x1 = (const float4*)(X + (size_t)s1 * DIM);
        float4 u0 = x0[lane];
        float4 u1 = x0[lane + 32];
        float4 v0 = x1[lane];
        float4 v1 = x1[lane + 32];
        a0.x += u0.x; a0.y += u0.y; a0.z += u0.z; a0.w += u0.w;
        a1.x += u1.x; a1.y += u1.y; a1.z += u1.z; a1.w += u1.w;
        a0.x += v0.x; a0.y += v0.y; a0.z += v0.z; a0.w += v0.w;
        a1.x += v1.x; a1.y += v1.y; a1.z += v1.z; a1.w += v1.w;
    }
    if (e < end) {
        int s = csr[e];
        const float4* xs = (const float4*)(X + (size_t)s * DIM);
        float4 u0 = xs[lane];
        float4 u1 = xs[lane + 32];
        a0.x += u0.x; a0.y += u0.y; a0.z += u0.z; a0.w += u0.w;
        a1.x += u1.x; a1.y += u1.y; a1.z += u1.z; a1.w += u1.w;
    }
    float4* yr = (float4*)(Y + (size_t)w * DIM);
    yr[lane] = a0;
    yr[lane + 32] = a1;
}

// ------------------------------ fused conv ---------------------------------
// 64x256 tile, 8 warps (2M x 4N), warp tile 32x64, BK=16 single-buffered W.

#define XP    260
#define XS_SZ (64 * XP)            // 16640 floats
#define WPAD  264
#define W_ST  (16 * WPAD)          // 4224 floats
#define CONV_SMEM_BYTES ((XS_SZ + W_ST) * 4)   // 83456 B -> 2 CTAs/SM

__device__ __forceinline__ float to_tf32(float x) {
    uint32_t u;
    asm("cvt.rna.tf32.f32 %0, %1;" : "=r"(u) : "f"(x));
    return __uint_as_float(u);
}

__device__ __forceinline__ void mma8(float* c, const uint32_t* a, const uint32_t* b) {
    asm volatile(
        "mma.sync.aligned.m16n8k8.row.col.f32.tf32.tf32.f32 "
        "{%0,%1,%2,%3},{%4,%5,%6,%7},{%8,%9},{%0,%1,%2,%3};\n"
        : "+f"(c[0]), "+f"(c[1]), "+f"(c[2]), "+f"(c[3])
        : "r"(a[0]), "r"(a[1]), "r"(a[2]), "r"(a[3]), "r"(b[0]), "r"(b[1]));
}

// C += XS(64x256 tf32) @ W(256x256), W staged via single-buffered smem chunks
__device__ __forceinline__ void gemm_k256(
    const float* __restrict__ W, const float* XS, float* WS,
    float (&c)[2][8][4], int tid, int wm, int wn, int g, int tq) {
    const int wq = tid & 63;
    const int wkb = tid >> 6;          // 0..3
    float4 rw[4];
    #pragma unroll
    for (int i = 0; i < 4; ++i)
        rw[i] = *(const float4*)(W + (long)(wkb + i * 4) * 256 + wq * 4);
    #pragma unroll
    for (int i = 0; i < 4; ++i) {
        float4 v = rw[i];
        v.x = to_tf32(v.x); v.y = to_tf32(v.y);
        v.z = to_tf32(v.z); v.w = to_tf32(v.w);
        *(float4*)(WS + (wkb + i * 4) * WPAD + wq * 4) = v;
    }
    __syncthreads();
    #pragma unroll 1
    for (int it = 0; it < 16; ++it) {
        if (it < 15) {
            int k0 = (it + 1) * 16;
            #pragma unroll
            for (int i = 0; i < 4; ++i)
                rw[i] = *(const float4*)(W + (long)(k0 + wkb + i * 4) * 256 + wq * 4);
        }
        #pragma unroll
        for (int kt = 0; kt < 2; ++kt) {
            int kb = it * 16 + kt * 8;
            int kw = kt * 8;
            uint32_t af[2][4], bf[8][2];
            #pragma unroll
            for (int mt = 0; mt < 2; ++mt) {
                int r0 = wm * 32 + mt * 16;
                af[mt][0] = __float_as_uint(XS[(r0 + g)     * XP + kb + tq]);
                af[mt][1] = __float_as_uint(XS[(r0 + 8 + g) * XP + kb + tq]);
                af[mt][2] = __float_as_uint(XS[(r0 + g)     * XP + kb + 4 + tq]);
                af[mt][3] = __float_as_uint(XS[(r0 + 8 + g) * XP + kb + 4 + tq]);
            }
            #pragma unroll
            for (int nt = 0; nt < 8; ++nt) {
                int n0 = wn * 64 + nt * 8;
                bf[nt][0] = __float_as_uint(WS[(kw + tq)     * WPAD + n0 + g]);
                bf[nt][1] = __float_as_uint(WS[(kw + 4 + tq) * WPAD + n0 + g]);
            }
            #pragma unroll
            for (int mt = 0; mt < 2; ++mt)
                #pragma unroll
                for (int nt = 0; nt < 8; ++nt)
                    mma8(c[mt][nt], af[mt], bf[nt]);
        }
        if (it < 15) {
            __syncthreads();
            #pragma unroll
            for (int i = 0; i < 4; ++i) {
                float4 v = rw[i];
                v.x = to_tf32(v.x); v.y = to_tf32(v.y);
                v.z = to_tf32(v.z); v.w = to_tf32(v.w);
                *(float4*)(WS + (wkb + i * 4) * WPAD + wq * 4) = v;
            }
            __syncthreads();
        }
    }
}

__global__ void __launch_bounds__(256, 2) k_conv(
    const float* __restrict__ A,   const float* __restrict__ bIn,
    const float* __restrict__ W1,  const float* __restrict__ b1,
    const float* __restrict__ lng, const float* __restrict__ lnb,
    const float* __restrict__ W2,  float* __restrict__ Out,
    int M, int reluLN, int hasG2) {
    extern __shared__ float sm[];
    float* XS = sm;
    float* WS = sm + XS_SZ;

    const int tid  = threadIdx.x;
    const int warp = tid >> 5, lane = tid & 31;
    const int wm = warp >> 2;
    const int wn = warp & 3;
    const int g  = lane >> 2;
    const int tq = lane & 3;
    const long blockRow = (long)blockIdx.x * 64;

    // ---- stage: XS = tf32( relu(A + bIn) ) ----
    #pragma unroll
    for (int i = 0; i < 16; ++i) {
        int id = i * 256 + tid;
        int row = id >> 6;
        int c4 = id & 63;
        long r = blockRow + row;
        if (r > M - 1) r = M - 1;
        float4 v = *(const float4*)(A + r * 256 + c4 * 4);
        float4 b = *(const float4*)(bIn + c4 * 4);
        v.x = to_tf32(fmaxf(v.x + b.x, 0.f));
        v.y = to_tf32(fmaxf(v.y + b.y, 0.f));
        v.z = to_tf32(fmaxf(v.z + b.z, 0.f));
        v.w = to_tf32(fmaxf(v.w + b.w, 0.f));
        *(float4*)(XS + row * XP + c4 * 4) = v;
    }
    // (gemm prologue's own __syncthreads orders this against all warps)

    float c[2][8][4];
    #pragma unroll
    for (int i = 0; i < 2; ++i)
        #pragma unroll
        for (int j = 0; j < 8; ++j)
            #pragma unroll
            for (int k = 0; k < 4; ++k) c[i][j][k] = 0.f;

    gemm_k256(W1, XS, WS, c, tid, wm, wn, g, tq);

    // ---- epilogue 1: bias (+relu) -> XS fp32 ----
    __syncthreads();
    #pragma unroll
    for (int mt = 0; mt < 2; ++mt) {
        int r0 = wm * 32 + mt * 16;
        #pragma unroll
        for (int nt = 0; nt < 8; ++nt) {
            int col = wn * 64 + nt * 8 + tq * 2;
            float2 bv = *(const float2*)(b1 + col);
            float v0 = c[mt][nt][0] + bv.x;
            float v1 = c[mt][nt][1] + bv.y;
            float v2 = c[mt][nt][2] + bv.x;
            float v3 = c[mt][nt][3] + bv.y;
            if (reluLN) {
                v0 = fmaxf(v0, 0.f); v1 = fmaxf(v1, 0.f);
                v2 = fmaxf(v2, 0.f); v3 = fmaxf(v3, 0.f);
            }
            XS[(r0 + g)     * XP + col]     = v0;
            XS[(r0 + g)     * XP + col + 1] = v1;
            XS[(r0 + 8 + g) * XP + col]     = v2;
            XS[(r0 + 8 + g) * XP + col + 1] = v3;
        }
    }
    __syncthreads();

    // ---- LayerNorm: warp handles rows warp*8..warp*8+7 ----
    {
        float4 ga  = *(const float4*)(lng + lane * 8);
        float4 gb  = *(const float4*)(lng + lane * 8 + 4);
        float4 bta = *(const float4*)(lnb + lane * 8);
        float4 btb = *(const float4*)(lnb + lane * 8 + 4);
        #pragma unroll 1
        for (int i = 0; i < 8; ++i) {
            int row = warp * 8 + i;
            long grow = blockRow + row;
            float4 v0 = *(const float4*)(XS + row * XP + lane * 8);
            float4 v1 = *(const float4*)(XS + row * XP + lane * 8 + 4);
            float s  = v0.x + v0.y + v0.z + v0.w + v1.x + v1.y + v1.z + v1.w;
            float ss = v0.x * v0.x + v0.y * v0.y + v0.z * v0.z + v0.w * v0.w +
                       v1.x * v1.x + v1.y * v1.y + v1.z * v1.z + v1.w * v1.w;
            #pragma unroll
            for (int o = 16; o >= 1; o >>= 1) {
                s  += __shfl_xor_sync(0xffffffffu, s, o);
                ss += __shfl_xor_sync(0xffffffffu, ss, o);
            }
            float mean = s * (1.f / 256.f);
            float var  = ss * (1.f / 256.f) - mean * mean;
            float rstd = rsqrtf(var + 1e-5f);
            float4 o0, o1;
            o0.x = (v0.x - mean) * rstd * ga.x + bta.x;
            o0.y = (v0.y - mean) * rstd * ga.y + bta.y;
            o0.z = (v0.z - mean) * rstd * ga.z + bta.z;
            o0.w = (v0.w - mean) * rstd * ga.w + bta.w;
            o1.x = (v1.x - mean) * rstd * gb.x + btb.x;
            o1.y = (v1.y - mean) * rstd * gb.y + btb.y;
            o1.z = (v1.z - mean) * rstd * gb.z + btb.z;
            o1.w = (v1.w - mean) * rstd * gb.w + btb.w;
            if (hasG2) {
                // h -> XS as tf32 for GEMM2
                o0.x = to_tf32(o0.x); o0.y = to_tf32(o0.y);
                o0.z = to_tf32(o0.z); o0.w = to_tf32(o0.w);
                o1.x = to_tf32(o1.x); o1.y = to_tf32(o1.y);
                o1.z = to_tf32(o1.z); o1.w = to_tf32(o1.w);
                *(float4*)(XS + row * XP + lane * 8)     = o0;
                *(float4*)(XS + row * XP + lane * 8 + 4) = o1;
            } else if (grow < M) {
                *(float4*)(Out + grow * 256 + lane * 8)     = o0;
                *(float4*)(Out + grow * 256 + lane * 8 + 4) = o1;
            }
        }
    }
    if (!hasG2) return;
    __syncthreads();

    // ---- GEMM2: u = h @ W2 (no bias), raw fp32 out ----
    #pragma unroll
    for (int i = 0; i < 2; ++i)
        #pragma unroll
        for (int j = 0; j < 8; ++j)
            #pragma unroll
            for (int k = 0; k < 4; ++k) c[i][j][k] = 0.f;

    gemm_k256(W2, XS, WS, c, tid, wm, wn, g, tq);

    #pragma unroll
    for (int mt = 0; mt < 2; ++mt) {
        long rb = blockRow + wm * 32 + mt * 16;
        long r0 = rb + g;
        long r1 = rb + 8 + g;
        #pragma unroll
        for (int nt = 0; nt < 8; ++nt) {
            int col = wn * 64 + nt * 8 + tq * 2;
            if (r0 < M) {
                float2 t = {c[mt][nt][0], c[mt][nt][1]};
                *(float2*)(Out + r0 * 256 + col) = t;
            }
            if (r1 < M) {
                float2 t = {c[mt][nt][2], c[mt][nt][3]};
                *(float2*)(Out + r1 * 256 + col) = t;
            }
        }
    }
}

// --------------------------------- driver ---------------------------------

extern "C" void kernel_launch(void* const* d_in, const int* in_sizes, int n_in,
                              void* d_out, int out_size) {
    const int*   xcat = (const int*)d_in[0];
    const int*   ei   = (const int*)d_in[1];
    const float* e0   = (const float*)d_in[2];
    const float* e1   = (const float*)d_in[3];
    const float* e2   = (const float*)d_in[4];
    const float* e3   = (const float*)d_in[5];
    const float* w1a  = (const float*)d_in[6];
    const float* b1a  = (const float*)d_in[7];
    const float* w1b  = (const float*)d_in[8];
    const float* b1b  = (const float*)d_in[9];
    const float* w2a  = (const float*)d_in[10];
    const float* b2a  = (const float*)d_in[11];
    const float* w2b  = (const float*)d_in[12];
    const float* b2b  = (const float*)d_in[13];
    const float* ln1g = (const float*)d_in[14];
    const float* ln1b = (const float*)d_in[15];
    const float* ln2g = (const float*)d_in[16];
    const float* ln2b = (const float*)d_in[17];

    int M = in_sizes[0] / 4;
    int E = in_sizes[1] / 2;
    int V = in_sizes[2] / 64;

    float *b0, *b1, *tab;
    int *deg, *rowptr, *cursor, *csr;
    cudaGetSymbolAddress((void**)&b0, g_b0);
    cudaGetSymbolAddress((void**)&b1, g_b1);
    cudaGetSymbolAddress((void**)&tab, g_tab);
    cudaGetSymbolAddress((void**)&deg, g_deg);
    cudaGetSymbolAddress((void**)&rowptr, g_rowptr);
    cudaGetSymbolAddress((void**)&cursor, g_cursor);
    cudaGetSymbolAddress((void**)&csr, g_csr);

    cudaFuncSetAttribute(k_conv, cudaFuncAttributeMaxDynamicSharedMemorySize,
                         CONV_SMEM_BYTES);

    int rowGrid = (M + 7) / 8;
    int convGrid = (M + 63) / 64;

    // CSR by dst
    k_zero<<<(M + 255) / 256, 256>>>(deg, M);
    k_count<<<(E + 255) / 256, 256>>>(ei, deg, E);
    k_scan<<<1, 1024>>>(deg, rowptr, cursor, M);
    k_fill<<<(E + 255) / 256, 256>>>(ei, cursor, csr, E);

    // embedding tables T_f = emb_f @ W1a_f, then z0 = sum_f T_f[cat_f]
    dim3 tgrid((V + 15) / 16, 4);
    k_tab<<<tgrid, 256>>>(e0, e1, e2, e3, w1a, tab, V);
    k_z0<<<(M * 64 + 255) / 256, 256>>>(xcat, tab, b0, M);

    // conv1: a1 = agg(z0); h = LN1(relu(relu(a1+b1a)@W1b+b1b)); u = h@W2a
    k_agg<<<rowGrid, 256>>>(b0, b1, rowptr, csr, M);
    k_conv<<<convGrid, 256, CONV_SMEM_BYTES>>>(b1, b1a, w1b, b1b,
                                               ln1g, ln1b, w2a, b0, M, 1, 1);

    // conv2: a2 = agg(u); out = LN2(relu(a2+b2a)@W2b+b2b)
    k_agg<<<rowGrid, 256>>>(b0, b1, rowptr, csr, M);
    k_conv<<<convGrid, 256, CONV_SMEM_BYTES>>>(b1, b2a, w2b, b2b,
                                               ln2g, ln2b, nullptr,
                                               (float*)d_out, M, 0, 0);
}